// round 1
// baseline (speedup 1.0000x reference)
#include <cuda_runtime.h>
#include <math.h>

#define N_NODES   100000
#define N_EDGES   1600000
#define N_FEAT    128
#define HIDDEN    16
#define EMBED     128
#define N_GRAPHS  64

// ---------------- scratch (device globals; no allocation allowed) ----------
__device__ __align__(16) float g_deg [N_NODES];
__device__ __align__(16) float g_dinv[N_NODES];
__device__ __align__(16) float g_h1   [N_NODES * HIDDEN];
__device__ __align__(16) float g_agg1 [N_NODES * HIDDEN];
__device__ __align__(16) float g_hrelu[N_NODES * HIDDEN];
__device__ __align__(16) float g_agg2 [N_NODES * HIDDEN];
__device__ float g_pool[N_GRAPHS * HIDDEN];
__device__ float g_cnt [N_GRAPHS];

// ---------------- K1: init (self-loop deg = 1, zero pool accumulators) -----
__global__ void k_init() {
    int i = blockIdx.x * blockDim.x + threadIdx.x;
    if (i < N_NODES)            g_deg[i]  = 1.0f;   // self-loop contributes 1
    if (i < N_GRAPHS * HIDDEN)  g_pool[i] = 0.0f;
    if (i < N_GRAPHS)           g_cnt[i]  = 0.0f;
}

// ---------------- K2: degree accumulation over edge dst --------------------
__global__ void k_deg(const int* __restrict__ dst) {
    int e = blockIdx.x * blockDim.x + threadIdx.x;
    if (e < N_EDGES) atomicAdd(&g_deg[dst[e]], 1.0f);
}

// ---------------- K3: dinv = rsqrt(deg) ------------------------------------
__global__ void k_dinv() {
    int i = blockIdx.x * blockDim.x + threadIdx.x;
    if (i < N_NODES) g_dinv[i] = rsqrtf(g_deg[i]);  // deg >= 1 always
}

// ---------------- K4: h1 = x @ W1, fused self-loop init of agg1 ------------
// block = 256 threads = 16 nodes x 16 hidden
__global__ void k_gemm1(const float4* __restrict__ x4,
                        const float*  __restrict__ W1) {
    __shared__ float  W1t[HIDDEN * 136];       // transposed, padded
    __shared__ float4 xs4[16 * (N_FEAT / 4)];  // 16 nodes x 128 feat

    int tid = threadIdx.x;
    // load W1 [128,16] -> W1t[j*136 + k]
    for (int idx = tid; idx < N_FEAT * HIDDEN; idx += 256) {
        int k = idx / HIDDEN, j = idx % HIDDEN;
        W1t[j * 136 + k] = W1[idx];
    }
    // stage 16 node rows of x
    int base4 = blockIdx.x * 16 * (N_FEAT / 4);
    for (int idx = tid; idx < 16 * (N_FEAT / 4); idx += 256)
        xs4[idx] = x4[base4 + idx];
    __syncthreads();

    int nl = tid >> 4;      // node within block
    int j  = tid & 15;      // hidden index
    const float4* wrow = (const float4*)(&W1t[j * 136]);
    float sum = 0.0f;
#pragma unroll
    for (int k4 = 0; k4 < N_FEAT / 4; k4++) {
        float4 xv = xs4[nl * (N_FEAT / 4) + k4];
        float4 wv = wrow[k4];
        sum += xv.x * wv.x + xv.y * wv.y + xv.z * wv.z + xv.w * wv.w;
    }
    int node = blockIdx.x * 16 + nl;
    float di = g_dinv[node];
    g_h1  [node * HIDDEN + j] = sum;
    g_agg1[node * HIDDEN + j] = sum * di * di;   // self-loop message
}

// ---------------- K5/K7: edge scatter, 4 lanes per edge, vec4 reduction ----
__global__ void k_scatter(int layer,
                          const int* __restrict__ src,
                          const int* __restrict__ dst) {
    int t = blockIdx.x * blockDim.x + threadIdx.x;
    if (t >= 4 * N_EDGES) return;
    int e = t >> 2;
    int q = t & 3;
    int s = __ldg(&src[e]);
    int d = __ldg(&dst[e]);
    float nrm = g_dinv[s] * g_dinv[d];

    const float4* h4 = (layer == 0) ? (const float4*)g_h1 : (const float4*)g_hrelu;
    float*       acc = (layer == 0) ? g_agg1 : g_agg2;

    float4 v = h4[s * 4 + q];
    v.x *= nrm; v.y *= nrm; v.z *= nrm; v.w *= nrm;
    float* p = acc + d * HIDDEN + q * 4;
    asm volatile("red.global.add.v4.f32 [%0], {%1,%2,%3,%4};"
                 :: "l"(p), "f"(v.x), "f"(v.y), "f"(v.z), "f"(v.w)
                 : "memory");
}

// ---------------- K6: relu(agg1 + b1), fused self-loop init of agg2 --------
__global__ void k_relu(const float* __restrict__ b1) {
    int i = blockIdx.x * blockDim.x + threadIdx.x;
    if (i >= N_NODES * HIDDEN) return;
    int node = i >> 4;
    int j    = i & 15;
    float v = fmaxf(g_agg1[i] + b1[j], 0.0f);
    g_hrelu[i] = v;
    float di = g_dinv[node];
    g_agg2[i] = v * di * di;   // self-loop message for layer 2
}

// ---------------- K8: pooling with run-length accumulation (batch sorted) --
#define POOL_CHUNK 32
__global__ void k_pool(const int* __restrict__ batch) {
    int t = blockIdx.x * blockDim.x + threadIdx.x;
    const int n_chunks = N_NODES / POOL_CHUNK;   // 3125
    if (t >= n_chunks * HIDDEN) return;
    int c = t >> 4;
    int j = t & 15;
    int n0 = c * POOL_CHUNK;

    int   curg = batch[n0];
    float acc  = 0.0f;
    float accc = 0.0f;
    for (int n = n0; n < n0 + POOL_CHUNK; n++) {
        int g = batch[n];
        if (g != curg) {
            atomicAdd(&g_pool[curg * HIDDEN + j], acc);
            if (j == 0) atomicAdd(&g_cnt[curg], accc);
            acc = 0.0f; accc = 0.0f; curg = g;
        }
        acc  += g_agg2[n * HIDDEN + j];
        accc += 1.0f;
    }
    atomicAdd(&g_pool[curg * HIDDEN + j], acc);
    if (j == 0) atomicAdd(&g_cnt[curg], accc);
}

// ---------------- K9: out = (pool/cnt) @ W2 + b2 ---------------------------
__global__ void k_final(const float* __restrict__ W2,
                        const float* __restrict__ b2,
                        float* __restrict__ out) {
    int t = blockIdx.x * blockDim.x + threadIdx.x;
    if (t >= N_GRAPHS * EMBED) return;
    int g = t >> 7;
    int e = t & 127;
    float inv = 1.0f / fmaxf(g_cnt[g], 1.0f);
    float sum = 0.0f;
#pragma unroll
    for (int k = 0; k < HIDDEN; k++)
        sum += g_pool[g * HIDDEN + k] * W2[k * EMBED + e];
    out[t] = b2[e] + inv * sum;
}

// ---------------- launch ----------------------------------------------------
extern "C" void kernel_launch(void* const* d_in, const int* in_sizes, int n_in,
                              void* d_out, int out_size) {
    const float* x     = (const float*)d_in[0];
    const int*   ei    = (const int*)  d_in[1];
    const int*   batch = (const int*)  d_in[2];
    const float* W1    = (const float*)d_in[3];
    const float* b1    = (const float*)d_in[4];
    const float* W2    = (const float*)d_in[5];
    const float* b2    = (const float*)d_in[6];
    float* out = (float*)d_out;

    const int* src = ei;
    const int* dst = ei + N_EDGES;

    k_init<<<(N_NODES + 255) / 256, 256>>>();
    k_deg <<<N_EDGES / 256, 256>>>(dst);
    k_dinv<<<(N_NODES + 255) / 256, 256>>>();
    k_gemm1<<<N_NODES / 16, 256>>>((const float4*)x, W1);
    k_scatter<<<(4 * N_EDGES) / 256, 256>>>(0, src, dst);
    k_relu<<<(N_NODES * HIDDEN) / 256, 256>>>(b1);
    k_scatter<<<(4 * N_EDGES) / 256, 256>>>(1, src, dst);
    k_pool<<<((N_NODES / POOL_CHUNK) * HIDDEN + 255) / 256, 256>>>(batch);
    k_final<<<(N_GRAPHS * EMBED) / 256, 256>>>(W2, b2, out);
}

// round 2
// speedup vs baseline: 1.2774x; 1.2774x over previous
#include <cuda_runtime.h>
#include <math.h>

#define N_NODES   100000
#define N_EDGES   1600000
#define N_FEAT    128
#define HIDDEN    16
#define EMBED     128
#define N_GRAPHS  64

// ---------------- scratch (device globals; no allocation allowed) ----------
__device__ __align__(16) float g_deg [N_NODES];
__device__ __align__(16) float g_dinv[N_NODES];
__device__ __align__(16) float g_nrm [N_EDGES];
__device__ __align__(16) float g_h1   [N_NODES * HIDDEN];
__device__ __align__(16) float g_agg1 [N_NODES * HIDDEN];
__device__ __align__(16) float g_hrelu[N_NODES * HIDDEN];
__device__ __align__(16) float g_agg2 [N_NODES * HIDDEN];
__device__ float g_pool[N_GRAPHS * HIDDEN];
__device__ float g_cnt [N_GRAPHS];

// ---------------- f32x2 packed-math helpers --------------------------------
__device__ __forceinline__ unsigned long long pack2(float a, float b) {
    unsigned long long r;
    asm("mov.b64 %0, {%1, %2};" : "=l"(r) : "f"(a), "f"(b));
    return r;
}
__device__ __forceinline__ unsigned long long fma2(unsigned long long a,
                                                   unsigned long long b,
                                                   unsigned long long c) {
    unsigned long long d;
    asm("fma.rn.f32x2 %0, %1, %2, %3;" : "=l"(d) : "l"(a), "l"(b), "l"(c));
    return d;
}
__device__ __forceinline__ unsigned long long mul2(unsigned long long a,
                                                   unsigned long long b) {
    unsigned long long d;
    asm("mul.rn.f32x2 %0, %1, %2;" : "=l"(d) : "l"(a), "l"(b));
    return d;
}

// ---------------- K1: init (self-loop deg = 1, zero pool accumulators) -----
__global__ void k_init() {
    int i = blockIdx.x * blockDim.x + threadIdx.x;
    if (i < N_NODES)            g_deg[i]  = 1.0f;
    if (i < N_GRAPHS * HIDDEN)  g_pool[i] = 0.0f;
    if (i < N_GRAPHS)           g_cnt[i]  = 0.0f;
}

// ---------------- K2: degree accumulation over edge dst --------------------
__global__ void k_deg(const int* __restrict__ dst) {
    int e = blockIdx.x * blockDim.x + threadIdx.x;
    if (e < N_EDGES) atomicAdd(&g_deg[dst[e]], 1.0f);
}

// ---------------- K3: dinv = rsqrt(deg) ------------------------------------
__global__ void k_dinv() {
    int i = blockIdx.x * blockDim.x + threadIdx.x;
    if (i < N_NODES) g_dinv[i] = rsqrtf(g_deg[i]);
}

// ---------------- K3b: per-edge norm = dinv[src]*dinv[dst] -----------------
__global__ void k_nrm(const int* __restrict__ src, const int* __restrict__ dst) {
    int e = blockIdx.x * blockDim.x + threadIdx.x;
    if (e < N_EDGES) g_nrm[e] = g_dinv[src[e]] * g_dinv[dst[e]];
}

// ---------------- K4: h1 = x @ W1, fused self-loop init of agg1 ------------
// 256 threads, 512 nodes/block, 2 nodes per thread, f32x2 math.
#define NPB   512
#define KC    16
#define PITCH 513
__global__ __launch_bounds__(256) void k_gemm1(const float4* __restrict__ x4,
                                               const float*  __restrict__ W1) {
    __shared__ float xs[KC * PITCH];                     // k-major x tile
    __shared__ unsigned long long Wp[N_FEAT * HIDDEN/2]; // packed W pairs

    int tid = threadIdx.x;
    for (int i = tid; i < N_FEAT * HIDDEN / 2; i += 256) {
        float2 w = ((const float2*)W1)[i];
        Wp[i] = pack2(w.x, w.y);
    }

    int base = blockIdx.x * NPB;
    int na = base + tid;
    int nb = na + 256;

    unsigned long long accA[8], accB[8];
    unsigned long long z = pack2(0.0f, 0.0f);
#pragma unroll
    for (int p = 0; p < 8; p++) { accA[p] = z; accB[p] = z; }

    for (int c = 0; c < N_FEAT / KC; c++) {
        __syncthreads();
#pragma unroll
        for (int i = 0; i < 8; i++) {
            int idx = i * 256 + tid;
            int q = idx & 3;
            int n = idx >> 2;
            int gn = base + n;
            if (gn >= N_NODES) gn = 0;
            float4 v = x4[gn * (N_FEAT/4) + c * (KC/4) + q];
            int kb = 4 * q;
            xs[(kb + 0) * PITCH + n] = v.x;
            xs[(kb + 1) * PITCH + n] = v.y;
            xs[(kb + 2) * PITCH + n] = v.z;
            xs[(kb + 3) * PITCH + n] = v.w;
        }
        __syncthreads();

#pragma unroll
        for (int k = 0; k < KC; k++) {
            float xa = xs[k * PITCH + tid];
            float xb = xs[k * PITCH + tid + 256];
            unsigned long long xa2 = pack2(xa, xa);
            unsigned long long xb2 = pack2(xb, xb);
            int kg = c * KC + k;
#pragma unroll
            for (int p2 = 0; p2 < 4; p2++) {
                ulonglong2 w = *((const ulonglong2*)&Wp[kg * 8 + 2 * p2]);
                accA[2*p2]   = fma2(xa2, w.x, accA[2*p2]);
                accA[2*p2+1] = fma2(xa2, w.y, accA[2*p2+1]);
                accB[2*p2]   = fma2(xb2, w.x, accB[2*p2]);
                accB[2*p2+1] = fma2(xb2, w.y, accB[2*p2+1]);
            }
        }
    }

    if (na < N_NODES) {
        float di = g_dinv[na];
        unsigned long long s2 = pack2(di * di, di * di);
#pragma unroll
        for (int p2 = 0; p2 < 4; p2++) {
            ulonglong2 v;  v.x  = accA[2*p2];           v.y  = accA[2*p2+1];
            ulonglong2 vs; vs.x = mul2(accA[2*p2], s2); vs.y = mul2(accA[2*p2+1], s2);
            *(ulonglong2*)&g_h1  [na * HIDDEN + 4 * p2] = v;
            *(ulonglong2*)&g_agg1[na * HIDDEN + 4 * p2] = vs;
        }
    }
    if (nb < N_NODES) {
        float di = g_dinv[nb];
        unsigned long long s2 = pack2(di * di, di * di);
#pragma unroll
        for (int p2 = 0; p2 < 4; p2++) {
            ulonglong2 v;  v.x  = accB[2*p2];           v.y  = accB[2*p2+1];
            ulonglong2 vs; vs.x = mul2(accB[2*p2], s2); vs.y = mul2(accB[2*p2+1], s2);
            *(ulonglong2*)&g_h1  [nb * HIDDEN + 4 * p2] = v;
            *(ulonglong2*)&g_agg1[nb * HIDDEN + 4 * p2] = vs;
        }
    }
}

// ---------------- K5/K7: edge scatter, 4 lanes per edge, vec4 reduction ----
__global__ void k_scatter(int layer,
                          const int* __restrict__ src,
                          const int* __restrict__ dst) {
    int t = blockIdx.x * blockDim.x + threadIdx.x;
    if (t >= 4 * N_EDGES) return;
    int e = t >> 2;
    int q = t & 3;
    int s = __ldg(&src[e]);
    int d = __ldg(&dst[e]);
    float nrm = __ldg(&g_nrm[e]);

    const float4* h4 = (layer == 0) ? (const float4*)g_h1 : (const float4*)g_hrelu;
    float*       acc = (layer == 0) ? g_agg1 : g_agg2;

    float4 v = h4[s * 4 + q];
    v.x *= nrm; v.y *= nrm; v.z *= nrm; v.w *= nrm;
    float* p = acc + d * HIDDEN + q * 4;
    asm volatile("red.global.add.v4.f32 [%0], {%1,%2,%3,%4};"
                 :: "l"(p), "f"(v.x), "f"(v.y), "f"(v.z), "f"(v.w)
                 : "memory");
}

// ---------------- K6: relu(agg1 + b1), fused self-loop init of agg2 --------
__global__ void k_relu(const float* __restrict__ b1) {
    int i = blockIdx.x * blockDim.x + threadIdx.x;
    if (i >= N_NODES * HIDDEN) return;
    int node = i >> 4;
    int j    = i & 15;
    float v = fmaxf(g_agg1[i] + b1[j], 0.0f);
    g_hrelu[i] = v;
    float di = g_dinv[node];
    g_agg2[i] = v * di * di;
}

// ---------------- K8: pooling with run-length accumulation (batch sorted) --
#define POOL_CHUNK 32
__global__ void k_pool(const int* __restrict__ batch) {
    int t = blockIdx.x * blockDim.x + threadIdx.x;
    const int n_chunks = N_NODES / POOL_CHUNK;
    if (t >= n_chunks * HIDDEN) return;
    int c = t >> 4;
    int j = t & 15;
    int n0 = c * POOL_CHUNK;

    int   curg = batch[n0];
    float acc  = 0.0f;
    float accc = 0.0f;
    for (int n = n0; n < n0 + POOL_CHUNK; n++) {
        int g = batch[n];
        if (g != curg) {
            atomicAdd(&g_pool[curg * HIDDEN + j], acc);
            if (j == 0) atomicAdd(&g_cnt[curg], accc);
            acc = 0.0f; accc = 0.0f; curg = g;
        }
        acc  += g_agg2[n * HIDDEN + j];
        accc += 1.0f;
    }
    atomicAdd(&g_pool[curg * HIDDEN + j], acc);
    if (j == 0) atomicAdd(&g_cnt[curg], accc);
}

// ---------------- K9: out = (pool/cnt) @ W2 + b2 ---------------------------
__global__ void k_final(const float* __restrict__ W2,
                        const float* __restrict__ b2,
                        float* __restrict__ out) {
    int t = blockIdx.x * blockDim.x + threadIdx.x;
    if (t >= N_GRAPHS * EMBED) return;
    int g = t >> 7;
    int e = t & 127;
    float inv = 1.0f / fmaxf(g_cnt[g], 1.0f);
    float sum = 0.0f;
#pragma unroll
    for (int k = 0; k < HIDDEN; k++)
        sum += g_pool[g * HIDDEN + k] * W2[k * EMBED + e];
    out[t] = b2[e] + inv * sum;
}

// ---------------- launch ----------------------------------------------------
extern "C" void kernel_launch(void* const* d_in, const int* in_sizes, int n_in,
                              void* d_out, int out_size) {
    const float* x     = (const float*)d_in[0];
    const int*   ei    = (const int*)  d_in[1];
    const int*   batch = (const int*)  d_in[2];
    const float* W1    = (const float*)d_in[3];
    const float* b1    = (const float*)d_in[4];
    const float* W2    = (const float*)d_in[5];
    const float* b2    = (const float*)d_in[6];
    float* out = (float*)d_out;

    const int* src = ei;
    const int* dst = ei + N_EDGES;

    k_init<<<(N_NODES + 255) / 256, 256>>>();
    k_deg <<<N_EDGES / 256, 256>>>(dst);
    k_dinv<<<(N_NODES + 255) / 256, 256>>>();
    k_nrm <<<N_EDGES / 256, 256>>>(src, dst);
    k_gemm1<<<(N_NODES + NPB - 1) / NPB, 256>>>((const float4*)x, W1);
    k_scatter<<<(4 * N_EDGES) / 256, 256>>>(0, src, dst);
    k_relu<<<(N_NODES * HIDDEN) / 256, 256>>>(b1);
    k_scatter<<<(4 * N_EDGES) / 256, 256>>>(1, src, dst);
    k_pool<<<((N_NODES / POOL_CHUNK) * HIDDEN + 255) / 256, 256>>>(batch);
    k_final<<<(N_GRAPHS * EMBED) / 256, 256>>>(W2, b2, out);
}

// round 5
// speedup vs baseline: 1.4619x; 1.1444x over previous
#include <cuda_runtime.h>
#include <math.h>

#define N_NODES   100000
#define N_EDGES   1600000
#define N_FEAT    128
#define HIDDEN    16
#define EMBED     128
#define N_GRAPHS  64

// ---------------- scratch (device globals; no allocation allowed) ----------
__device__ __align__(16) float g_deg [N_NODES];
__device__ __align__(16) float g_dinv[N_NODES];
__device__ __align__(16) float g_nrm [N_EDGES];
__device__ __align__(16) float g_h1   [N_NODES * HIDDEN];
__device__ __align__(16) float g_agg1 [N_NODES * HIDDEN];
__device__ __align__(16) float g_hrelu[N_NODES * HIDDEN];
__device__ __align__(16) float g_agg2 [N_NODES * HIDDEN];
__device__ __align__(16) float g_pool[N_GRAPHS * HIDDEN];
__device__ __align__(16) float g_cnt [N_GRAPHS];

// ---------------- f32x2 packed-math helpers --------------------------------
__device__ __forceinline__ unsigned long long pack2(float a, float b) {
    unsigned long long r;
    asm("mov.b64 %0, {%1, %2};" : "=l"(r) : "f"(a), "f"(b));
    return r;
}
__device__ __forceinline__ unsigned long long fma2(unsigned long long a,
                                                   unsigned long long b,
                                                   unsigned long long c) {
    unsigned long long d;
    asm("fma.rn.f32x2 %0, %1, %2, %3;" : "=l"(d) : "l"(a), "l"(b), "l"(c));
    return d;
}
__device__ __forceinline__ unsigned long long mul2(unsigned long long a,
                                                   unsigned long long b) {
    unsigned long long d;
    asm("mul.rn.f32x2 %0, %1, %2;" : "=l"(d) : "l"(a), "l"(b));
    return d;
}

// ---------------- K_zero: reset ALL cross-call accumulators ----------------
// g_deg (100000 floats), g_pool (1024 floats), g_cnt (64 floats)
__global__ void k_zero() {
    int i = blockIdx.x * blockDim.x + threadIdx.x;   // over float4s
    float4 z = make_float4(0.f, 0.f, 0.f, 0.f);
    if (i < N_NODES / 4) ((float4*)g_deg)[i] = z;
    if (i < N_GRAPHS * HIDDEN / 4) ((float4*)g_pool)[i] = z;
    if (i < N_GRAPHS / 4) ((float4*)g_cnt)[i] = z;
}

// ---------------- K_main: fused [GEMM1 h1 = x@W1] + [degree atomics] -------
// blocks [0, GEMM_BLOCKS): GEMM, 512 nodes/block, 2 nodes/thread, f32x2 math
// blocks [GEMM_BLOCKS, ...): degree accumulation
#define NPB   512
#define KC    16
#define PITCH 513
#define GEMM_BLOCKS ((N_NODES + NPB - 1) / NPB)   // 196
#define DEG_BLOCKS  (N_EDGES / 256)               // 6250
__global__ __launch_bounds__(256) void k_main(const float4* __restrict__ x4,
                                              const float*  __restrict__ W1,
                                              const int*    __restrict__ dst) {
    if (blockIdx.x >= GEMM_BLOCKS) {
        int e = (blockIdx.x - GEMM_BLOCKS) * 256 + threadIdx.x;
        if (e < N_EDGES) atomicAdd(&g_deg[dst[e]], 1.0f);
        return;
    }

    __shared__ float xs[KC * PITCH];                     // k-major x tile
    __shared__ unsigned long long Wp[N_FEAT * HIDDEN/2]; // packed W pairs

    int tid = threadIdx.x;
    for (int i = tid; i < N_FEAT * HIDDEN / 2; i += 256) {
        float2 w = ((const float2*)W1)[i];
        Wp[i] = pack2(w.x, w.y);
    }

    int base = blockIdx.x * NPB;
    int na = base + tid;
    int nb = na + 256;

    unsigned long long accA[8], accB[8];
    unsigned long long z = pack2(0.0f, 0.0f);
#pragma unroll
    for (int p = 0; p < 8; p++) { accA[p] = z; accB[p] = z; }

    for (int c = 0; c < N_FEAT / KC; c++) {
        __syncthreads();
#pragma unroll
        for (int i = 0; i < 8; i++) {
            int idx = i * 256 + tid;
            int q = idx & 3;
            int n = idx >> 2;
            int gn = base + n;
            if (gn >= N_NODES) gn = 0;
            float4 v = x4[gn * (N_FEAT/4) + c * (KC/4) + q];
            int kb = 4 * q;
            xs[(kb + 0) * PITCH + n] = v.x;
            xs[(kb + 1) * PITCH + n] = v.y;
            xs[(kb + 2) * PITCH + n] = v.z;
            xs[(kb + 3) * PITCH + n] = v.w;
        }
        __syncthreads();

#pragma unroll
        for (int k = 0; k < KC; k++) {
            float xa = xs[k * PITCH + tid];
            float xb = xs[k * PITCH + tid + 256];
            unsigned long long xa2 = pack2(xa, xa);
            unsigned long long xb2 = pack2(xb, xb);
            int kg = c * KC + k;
#pragma unroll
            for (int p2 = 0; p2 < 4; p2++) {
                ulonglong2 w = *((const ulonglong2*)&Wp[kg * 8 + 2 * p2]);
                accA[2*p2]   = fma2(xa2, w.x, accA[2*p2]);
                accA[2*p2+1] = fma2(xa2, w.y, accA[2*p2+1]);
                accB[2*p2]   = fma2(xb2, w.x, accB[2*p2]);
                accB[2*p2+1] = fma2(xb2, w.y, accB[2*p2+1]);
            }
        }
    }

    if (na < N_NODES) {
#pragma unroll
        for (int p2 = 0; p2 < 4; p2++) {
            ulonglong2 v; v.x = accA[2*p2]; v.y = accA[2*p2+1];
            *(ulonglong2*)&g_h1[na * HIDDEN + 4 * p2] = v;
        }
    }
    if (nb < N_NODES) {
#pragma unroll
        for (int p2 = 0; p2 < 4; p2++) {
            ulonglong2 v; v.x = accB[2*p2]; v.y = accB[2*p2+1];
            *(ulonglong2*)&g_h1[nb * HIDDEN + 4 * p2] = v;
        }
    }
}

// ---------------- K_self: dinv = rsqrt(1+deg); agg1 = h1/(1+deg) -----------
__global__ void k_self() {
    int idx = blockIdx.x * blockDim.x + threadIdx.x;   // over float4s of agg1
    if (idx < N_NODES) {
        g_dinv[idx] = rsqrtf(1.0f + g_deg[idx]);
    }
    if (idx < N_NODES * 4) {
        int node = idx >> 2;
        float s = 1.0f / (1.0f + g_deg[node]);          // dinv^2
        float4 v = ((const float4*)g_h1)[idx];
        v.x *= s; v.y *= s; v.z *= s; v.w *= s;
        ((float4*)g_agg1)[idx] = v;
    }
}

// ---------------- K_scatter1: nrm compute + gather h1 + red agg1 -----------
__global__ void k_scatter1(const int* __restrict__ src,
                           const int* __restrict__ dst) {
    int t = blockIdx.x * blockDim.x + threadIdx.x;
    if (t >= 4 * N_EDGES) return;
    int e = t >> 2;
    int q = t & 3;
    int s = __ldg(&src[e]);
    int d = __ldg(&dst[e]);
    float nrm = __ldg(&g_dinv[s]) * __ldg(&g_dinv[d]);  // 4 lanes coalesce
    if (q == 0) g_nrm[e] = nrm;                          // save for scatter2

    float4 v = ((const float4*)g_h1)[s * 4 + q];
    v.x *= nrm; v.y *= nrm; v.z *= nrm; v.w *= nrm;
    float* p = g_agg1 + d * HIDDEN + q * 4;
    asm volatile("red.global.add.v4.f32 [%0], {%1,%2,%3,%4};"
                 :: "l"(p), "f"(v.x), "f"(v.y), "f"(v.z), "f"(v.w)
                 : "memory");
}

// ---------------- K_relu: hrelu = relu(agg1+b1); agg2 = hrelu*dinv^2 -------
__global__ void k_relu(const float* __restrict__ b1) {
    int idx = blockIdx.x * blockDim.x + threadIdx.x;    // over float4s
    if (idx >= N_NODES * 4) return;
    int node = idx >> 2;
    float4 bv = ((const float4*)b1)[idx & 3];
    float4 a  = ((const float4*)g_agg1)[idx];
    a.x = fmaxf(a.x + bv.x, 0.0f);
    a.y = fmaxf(a.y + bv.y, 0.0f);
    a.z = fmaxf(a.z + bv.z, 0.0f);
    a.w = fmaxf(a.w + bv.w, 0.0f);
    ((float4*)g_hrelu)[idx] = a;
    float di = g_dinv[node];
    float s = di * di;
    a.x *= s; a.y *= s; a.z *= s; a.w *= s;
    ((float4*)g_agg2)[idx] = a;
}

// ---------------- K_scatter2: reload nrm + gather hrelu + red agg2 ---------
__global__ void k_scatter2(const int* __restrict__ src,
                           const int* __restrict__ dst) {
    int t = blockIdx.x * blockDim.x + threadIdx.x;
    if (t >= 4 * N_EDGES) return;
    int e = t >> 2;
    int q = t & 3;
    int s = __ldg(&src[e]);
    int d = __ldg(&dst[e]);
    float nrm = __ldg(&g_nrm[e]);

    float4 v = ((const float4*)g_hrelu)[s * 4 + q];
    v.x *= nrm; v.y *= nrm; v.z *= nrm; v.w *= nrm;
    float* p = g_agg2 + d * HIDDEN + q * 4;
    asm volatile("red.global.add.v4.f32 [%0], {%1,%2,%3,%4};"
                 :: "l"(p), "f"(v.x), "f"(v.y), "f"(v.z), "f"(v.w)
                 : "memory");
}

// ---------------- K_pool: run-length accumulation (batch sorted) -----------
#define POOL_CHUNK 32
__global__ void k_pool(const int* __restrict__ batch) {
    int t = blockIdx.x * blockDim.x + threadIdx.x;
    const int n_chunks = N_NODES / POOL_CHUNK;
    if (t >= n_chunks * HIDDEN) return;
    int c = t >> 4;
    int j = t & 15;
    int n0 = c * POOL_CHUNK;

    int   curg = batch[n0];
    float acc  = 0.0f;
    float accc = 0.0f;
    for (int n = n0; n < n0 + POOL_CHUNK; n++) {
        int g = batch[n];
        if (g != curg) {
            atomicAdd(&g_pool[curg * HIDDEN + j], acc);
            if (j == 0) atomicAdd(&g_cnt[curg], accc);
            acc = 0.0f; accc = 0.0f; curg = g;
        }
        acc  += g_agg2[n * HIDDEN + j];
        accc += 1.0f;
    }
    atomicAdd(&g_pool[curg * HIDDEN + j], acc);
    if (j == 0) atomicAdd(&g_cnt[curg], accc);
}

// ---------------- K_final: out = (pool/cnt) @ W2 + b2 ----------------------
__global__ void k_final(const float* __restrict__ W2,
                        const float* __restrict__ b2,
                        float* __restrict__ out) {
    int t = blockIdx.x * blockDim.x + threadIdx.x;
    if (t >= N_GRAPHS * EMBED) return;
    int g = t >> 7;
    int e = t & 127;
    float inv = 1.0f / fmaxf(g_cnt[g], 1.0f);
    float sum = 0.0f;
#pragma unroll
    for (int k = 0; k < HIDDEN; k++)
        sum += g_pool[g * HIDDEN + k] * W2[k * EMBED + e];
    out[t] = b2[e] + inv * sum;
}

// ---------------- launch ----------------------------------------------------
extern "C" void kernel_launch(void* const* d_in, const int* in_sizes, int n_in,
                              void* d_out, int out_size) {
    const float* x     = (const float*)d_in[0];
    const int*   ei    = (const int*)  d_in[1];
    const int*   batch = (const int*)  d_in[2];
    const float* W1    = (const float*)d_in[3];
    const float* b1    = (const float*)d_in[4];
    const float* W2    = (const float*)d_in[5];
    const float* b2    = (const float*)d_in[6];
    float* out = (float*)d_out;

    const int* src = ei;
    const int* dst = ei + N_EDGES;

    k_zero<<<(N_NODES / 4 + 255) / 256, 256>>>();
    k_main<<<GEMM_BLOCKS + DEG_BLOCKS, 256>>>((const float4*)x, W1, dst);
    k_self<<<(N_NODES * 4 + 255) / 256, 256>>>();
    k_scatter1<<<(4 * N_EDGES) / 256, 256>>>(src, dst);
    k_relu<<<(N_NODES * 4 + 255) / 256, 256>>>(b1);
    k_scatter2<<<(4 * N_EDGES) / 256, 256>>>(src, dst);
    k_pool<<<((N_NODES / POOL_CHUNK) * HIDDEN + 255) / 256, 256>>>(batch);
    k_final<<<(N_GRAPHS * EMBED) / 256, 256>>>(W2, b2, out);
}

// round 6
// speedup vs baseline: 1.6335x; 1.1173x over previous
#include <cuda_runtime.h>
#include <cuda_fp16.h>
#include <math.h>

#define N_NODES   100000
#define N_EDGES   1600000
#define N_FEAT    128
#define HIDDEN    16
#define EMBED     128
#define N_GRAPHS  64

// ---------------- scratch (device globals; no allocation allowed) ----------
__device__ __align__(16) float  g_deg [N_NODES];
__device__ __align__(16) float  g_dinv[N_NODES];
__device__ __align__(16) float  g_h1  [N_NODES * HIDDEN];
__device__ __align__(16) __half g_hs1 [N_NODES * HIDDEN];   // dinv[n]*h1[n], fp16
__device__ __align__(16) float  g_agg1[N_NODES * HIDDEN];
__device__ __align__(16) __half g_hs2 [N_NODES * HIDDEN];   // dinv[n]*hrelu[n], fp16
__device__ __align__(16) float  g_agg2[N_NODES * HIDDEN];
__device__ __align__(16) float  g_pool[N_GRAPHS * HIDDEN];
__device__ __align__(16) float  g_cnt [N_GRAPHS];

// ---------------- f32x2 packed-math helpers --------------------------------
__device__ __forceinline__ unsigned long long pack2(float a, float b) {
    unsigned long long r;
    asm("mov.b64 %0, {%1, %2};" : "=l"(r) : "f"(a), "f"(b));
    return r;
}
__device__ __forceinline__ unsigned long long fma2(unsigned long long a,
                                                   unsigned long long b,
                                                   unsigned long long c) {
    unsigned long long d;
    asm("fma.rn.f32x2 %0, %1, %2, %3;" : "=l"(d) : "l"(a), "l"(b), "l"(c));
    return d;
}

// ---------------- K_zero: reset ALL cross-call accumulators ----------------
__global__ void k_zero() {
    int i = blockIdx.x * blockDim.x + threadIdx.x;   // over float4s
    float4 z = make_float4(0.f, 0.f, 0.f, 0.f);
    if (i < N_NODES / 4) ((float4*)g_deg)[i] = z;
    if (i < N_GRAPHS * HIDDEN / 4) ((float4*)g_pool)[i] = z;
    if (i < N_GRAPHS / 4) ((float4*)g_cnt)[i] = z;
}

// ---------------- K_main: fused [GEMM1 h1 = x@W1] + [degree atomics] -------
#define NPB   512
#define KC    16
#define PITCH 513
#define GEMM_BLOCKS ((N_NODES + NPB - 1) / NPB)   // 196
#define DEG_BLOCKS  (N_EDGES / 256)               // 6250
__global__ __launch_bounds__(256) void k_main(const float4* __restrict__ x4,
                                              const float*  __restrict__ W1,
                                              const int*    __restrict__ dst) {
    if (blockIdx.x >= GEMM_BLOCKS) {
        int e = (blockIdx.x - GEMM_BLOCKS) * 256 + threadIdx.x;
        if (e < N_EDGES) atomicAdd(&g_deg[dst[e]], 1.0f);
        return;
    }

    __shared__ float xs[KC * PITCH];                     // k-major x tile
    __shared__ unsigned long long Wp[N_FEAT * HIDDEN/2]; // packed W pairs

    int tid = threadIdx.x;
    for (int i = tid; i < N_FEAT * HIDDEN / 2; i += 256) {
        float2 w = ((const float2*)W1)[i];
        Wp[i] = pack2(w.x, w.y);
    }

    int base = blockIdx.x * NPB;
    int na = base + tid;
    int nb = na + 256;

    unsigned long long accA[8], accB[8];
    unsigned long long z = pack2(0.0f, 0.0f);
#pragma unroll
    for (int p = 0; p < 8; p++) { accA[p] = z; accB[p] = z; }

    for (int c = 0; c < N_FEAT / KC; c++) {
        __syncthreads();
#pragma unroll
        for (int i = 0; i < 8; i++) {
            int idx = i * 256 + tid;
            int q = idx & 3;
            int n = idx >> 2;
            int gn = base + n;
            if (gn >= N_NODES) gn = 0;
            float4 v = x4[gn * (N_FEAT/4) + c * (KC/4) + q];
            int kb = 4 * q;
            xs[(kb + 0) * PITCH + n] = v.x;
            xs[(kb + 1) * PITCH + n] = v.y;
            xs[(kb + 2) * PITCH + n] = v.z;
            xs[(kb + 3) * PITCH + n] = v.w;
        }
        __syncthreads();

#pragma unroll
        for (int k = 0; k < KC; k++) {
            float xa = xs[k * PITCH + tid];
            float xb = xs[k * PITCH + tid + 256];
            unsigned long long xa2 = pack2(xa, xa);
            unsigned long long xb2 = pack2(xb, xb);
            int kg = c * KC + k;
#pragma unroll
            for (int p2 = 0; p2 < 4; p2++) {
                ulonglong2 w = *((const ulonglong2*)&Wp[kg * 8 + 2 * p2]);
                accA[2*p2]   = fma2(xa2, w.x, accA[2*p2]);
                accA[2*p2+1] = fma2(xa2, w.y, accA[2*p2+1]);
                accB[2*p2]   = fma2(xb2, w.x, accB[2*p2]);
                accB[2*p2+1] = fma2(xb2, w.y, accB[2*p2+1]);
            }
        }
    }

    if (na < N_NODES) {
#pragma unroll
        for (int p2 = 0; p2 < 4; p2++) {
            ulonglong2 v; v.x = accA[2*p2]; v.y = accA[2*p2+1];
            *(ulonglong2*)&g_h1[na * HIDDEN + 4 * p2] = v;
        }
    }
    if (nb < N_NODES) {
#pragma unroll
        for (int p2 = 0; p2 < 4; p2++) {
            ulonglong2 v; v.x = accB[2*p2]; v.y = accB[2*p2+1];
            *(ulonglong2*)&g_h1[nb * HIDDEN + 4 * p2] = v;
        }
    }
}

// ---- K_self: dinv = rsqrt(1+deg); hs1 = dinv*h1 (fp16); agg1 = dinv*h1 ----
__global__ void k_self() {
    int idx = blockIdx.x * blockDim.x + threadIdx.x;   // over float4s (4/node)
    if (idx >= N_NODES * 4) return;
    int node = idx >> 2;
    int q    = idx & 3;
    float di = rsqrtf(1.0f + g_deg[node]);
    if (q == 0) g_dinv[node] = di;
    float4 v = ((const float4*)g_h1)[idx];
    v.x *= di; v.y *= di; v.z *= di; v.w *= di;
    ((float4*)g_agg1)[idx] = v;                        // self-loop seed (pre dinv[d])
    __half2 h0 = __floats2half2_rn(v.x, v.y);
    __half2 h1 = __floats2half2_rn(v.z, v.w);
    uint2 u; u.x = *(unsigned*)&h0; u.y = *(unsigned*)&h1;
    ((uint2*)g_hs1)[idx] = u;
}

// ---- K_scatter1: gather hs1 (fp16) + red agg1 (no per-edge norm!) ---------
__global__ void k_scatter1(const int* __restrict__ src,
                           const int* __restrict__ dst) {
    int t = blockIdx.x * blockDim.x + threadIdx.x;
    if (t >= 4 * N_EDGES) return;
    int e = t >> 2;
    int q = t & 3;
    int s = __ldg(&src[e]);
    int d = __ldg(&dst[e]);
    uint2 u = __ldg(&((const uint2*)g_hs1)[s * 4 + q]);  // 4 halves, 8B
    float2 f0 = __half22float2(*(__half2*)&u.x);
    float2 f1 = __half22float2(*(__half2*)&u.y);
    float* p = g_agg1 + d * HIDDEN + q * 4;
    asm volatile("red.global.add.v4.f32 [%0], {%1,%2,%3,%4};"
                 :: "l"(p), "f"(f0.x), "f"(f0.y), "f"(f1.x), "f"(f1.y)
                 : "memory");
}

// ---- K_relu: pre = dinv*agg1 + b1; h = relu(pre); hs2 = dinv*h; agg2 = hs2 -
__global__ void k_relu(const float* __restrict__ b1) {
    int idx = blockIdx.x * blockDim.x + threadIdx.x;    // over float4s
    if (idx >= N_NODES * 4) return;
    int node = idx >> 2;
    float di = g_dinv[node];
    float4 bv = ((const float4*)b1)[idx & 3];
    float4 a  = ((const float4*)g_agg1)[idx];
    a.x = fmaxf(fmaf(di, a.x, bv.x), 0.0f);
    a.y = fmaxf(fmaf(di, a.y, bv.y), 0.0f);
    a.z = fmaxf(fmaf(di, a.z, bv.z), 0.0f);
    a.w = fmaxf(fmaf(di, a.w, bv.w), 0.0f);
    a.x *= di; a.y *= di; a.z *= di; a.w *= di;         // hs2 = dinv*hrelu
    ((float4*)g_agg2)[idx] = a;                          // self-loop seed
    __half2 h0 = __floats2half2_rn(a.x, a.y);
    __half2 h1 = __floats2half2_rn(a.z, a.w);
    uint2 u; u.x = *(unsigned*)&h0; u.y = *(unsigned*)&h1;
    ((uint2*)g_hs2)[idx] = u;
}

// ---- K_scatter2: gather hs2 (fp16) + red agg2 ------------------------------
__global__ void k_scatter2(const int* __restrict__ src,
                           const int* __restrict__ dst) {
    int t = blockIdx.x * blockDim.x + threadIdx.x;
    if (t >= 4 * N_EDGES) return;
    int e = t >> 2;
    int q = t & 3;
    int s = __ldg(&src[e]);
    int d = __ldg(&dst[e]);
    uint2 u = __ldg(&((const uint2*)g_hs2)[s * 4 + q]);
    float2 f0 = __half22float2(*(__half2*)&u.x);
    float2 f1 = __half22float2(*(__half2*)&u.y);
    float* p = g_agg2 + d * HIDDEN + q * 4;
    asm volatile("red.global.add.v4.f32 [%0], {%1,%2,%3,%4};"
                 :: "l"(p), "f"(f0.x), "f"(f0.y), "f"(f1.x), "f"(f1.y)
                 : "memory");
}

// ---- K_pool: pool += dinv[n]*agg2[n]  (batch sorted, run-length) ----------
#define POOL_CHUNK 32
__global__ void k_pool(const int* __restrict__ batch) {
    int t = blockIdx.x * blockDim.x + threadIdx.x;
    const int n_chunks = N_NODES / POOL_CHUNK;
    if (t >= n_chunks * HIDDEN) return;
    int c = t >> 4;
    int j = t & 15;
    int n0 = c * POOL_CHUNK;

    int   curg = batch[n0];
    float acc  = 0.0f;
    float accc = 0.0f;
    for (int n = n0; n < n0 + POOL_CHUNK; n++) {
        int g = batch[n];
        if (g != curg) {
            atomicAdd(&g_pool[curg * HIDDEN + j], acc);
            if (j == 0) atomicAdd(&g_cnt[curg], accc);
            acc = 0.0f; accc = 0.0f; curg = g;
        }
        acc  = fmaf(g_dinv[n], g_agg2[n * HIDDEN + j], acc);
        accc += 1.0f;
    }
    atomicAdd(&g_pool[curg * HIDDEN + j], acc);
    if (j == 0) atomicAdd(&g_cnt[curg], accc);
}

// ---- K_final: out = (pool/cnt) @ W2 + b2 -----------------------------------
__global__ void k_final(const float* __restrict__ W2,
                        const float* __restrict__ b2,
                        float* __restrict__ out) {
    int t = blockIdx.x * blockDim.x + threadIdx.x;
    if (t >= N_GRAPHS * EMBED) return;
    int g = t >> 7;
    int e = t & 127;
    float inv = 1.0f / fmaxf(g_cnt[g], 1.0f);
    float sum = 0.0f;
#pragma unroll
    for (int k = 0; k < HIDDEN; k++)
        sum += g_pool[g * HIDDEN + k] * W2[k * EMBED + e];
    out[t] = b2[e] + inv * sum;
}

// ---------------- launch ----------------------------------------------------
extern "C" void kernel_launch(void* const* d_in, const int* in_sizes, int n_in,
                              void* d_out, int out_size) {
    const float* x     = (const float*)d_in[0];
    const int*   ei    = (const int*)  d_in[1];
    const int*   batch = (const int*)  d_in[2];
    const float* W1    = (const float*)d_in[3];
    const float* b1    = (const float*)d_in[4];
    const float* W2    = (const float*)d_in[5];
    const float* b2    = (const float*)d_in[6];
    float* out = (float*)d_out;

    const int* src = ei;
    const int* dst = ei + N_EDGES;

    k_zero<<<(N_NODES / 4 + 255) / 256, 256>>>();
    k_main<<<GEMM_BLOCKS + DEG_BLOCKS, 256>>>((const float4*)x, W1, dst);
    k_self<<<(N_NODES * 4 + 255) / 256, 256>>>();
    k_scatter1<<<(4 * N_EDGES) / 256, 256>>>(src, dst);
    k_relu<<<(N_NODES * 4 + 255) / 256, 256>>>(b1);
    k_scatter2<<<(4 * N_EDGES) / 256, 256>>>(src, dst);
    k_pool<<<((N_NODES / POOL_CHUNK) * HIDDEN + 255) / 256, 256>>>(batch);
    k_final<<<(N_GRAPHS * EMBED) / 256, 256>>>(W2, b2, out);
}